// round 15
// baseline (speedup 1.0000x reference)
#include <cuda_runtime.h>
#include <math.h>

typedef unsigned long long ull;

#define NDIM 512
#define DDIM 784
#define CDIM 10
#define ITERS 40
#define QMAX 127.0f

#define MT 8          // row tiles (64 rows each)
#define NT 16         // column groups (8 cols each)
#define GRID 64       // 8 tiles x 8 group-pairs; each CTA runs groups gj and gj+8
#define TPB 512
#define ZSTR 12       // padded z row stride (8 used + 4 pad)

// shared layout (float offsets)
#define S_ZA   0          // group A z: 512*12 = 6144
#define S_ZB   6144       // group B z: 6144
#define S_REDA 12288      // 16 warps * 640 = 10240 (single-buffered, barrier-protected)
#define S_REDB 22528      // 10240
#define S_UX   32768      // 1024 (A: [0,512), B: [512,1024))
#define SMEM_FLOATS 33792
#define SMEM_BYTES (SMEM_FLOATS*4)
// Phase B scratch overlaps sZ/sRed: xs @0 (12544), uq @12544 (7424, ends 19968)

// ---- device globals (scratch) ----
__device__ float g_zA[NDIM*128];                 // z_j, j odd
__device__ float g_zB[NDIM*128];                 // z_j, j even
__device__ unsigned g_rgen[2][NT*NDIM];          // per-row generation words
__device__ unsigned g_maxW, g_maxU, g_maxB;      // idempotent atomicMax
__device__ unsigned g_gcnt, g_ggen;              // grid barrier (used once)

// -------- grid barrier (prologue only) --------
__device__ __forceinline__ void gbar(unsigned* cnt, unsigned* gen, unsigned expected) {
    __syncthreads();
    if (threadIdx.x == 0) {
        unsigned snap, t;
        asm volatile("ld.acquire.gpu.global.u32 %0, [%1];" : "=r"(snap) : "l"(gen) : "memory");
        asm volatile("atom.acq_rel.gpu.global.add.u32 %0, [%1], %2;"
                     : "=r"(t) : "l"(cnt), "r"(1u) : "memory");
        if (t == expected - 1u) {
            asm volatile("st.relaxed.gpu.global.u32 [%0], %1;" :: "l"(cnt), "r"(0u) : "memory");
            asm volatile("red.release.gpu.global.add.u32 [%0], %1;" :: "l"(gen), "r"(1u) : "memory");
        } else {
            unsigned g;
            do {
                asm volatile("ld.acquire.gpu.global.u32 %0, [%1];" : "=r"(g) : "l"(gen) : "memory");
            } while (g == snap);
        }
    }
    __syncthreads();
}

// -------- gen-word primitives --------
__device__ __forceinline__ void gen_store(unsigned* f, unsigned v) {
    asm volatile("st.release.gpu.global.u32 [%0], %1;" :: "l"(f), "r"(v) : "memory");
}
__device__ __forceinline__ unsigned gen_acq(const unsigned* f) {
    unsigned v;
    asm volatile("ld.acquire.gpu.global.u32 %0, [%1];" : "=r"(v) : "l"(f) : "memory");
    return v;
}

// -------- f32x2 helpers --------
__device__ __forceinline__ ull pk2(float x){
    ull d; asm("mov.b64 %0, {%1,%1};" : "=l"(d) : "r"(__float_as_uint(x))); return d;
}
__device__ __forceinline__ void fma2(ull& d, ull a, ull b){
    asm("fma.rn.f32x2 %0, %1, %2, %3;" : "=l"(d) : "l"(a), "l"(b), "l"(d));
}
__device__ __forceinline__ float warpmax(float v){
    #pragma unroll
    for (int o = 16; o; o >>= 1) v = fmaxf(v, __shfl_xor_sync(0xffffffffu, v, o));
    return v;
}

extern "C" __global__ void __launch_bounds__(TPB, 1)
mondeq_kernel(const float* __restrict__ W, const float* __restrict__ U,
              const float* __restrict__ bvec, const float* __restrict__ x,
              const float* __restrict__ Wc, const float* __restrict__ bcv,
              float* __restrict__ out)
{
    extern __shared__ float sm[];
    float* sZA   = sm + S_ZA;
    float* sZB   = sm + S_ZB;
    float* sRedA = sm + S_REDA;
    float* sRedB = sm + S_REDB;
    float* sUx   = sm + S_UX;

    const int tid  = threadIdx.x;
    const int cta  = blockIdx.x;
    const int mi   = cta & (MT - 1);   // row tile 0..7
    const int gj   = cta >> 3;         // group-pair 0..7: groups gj (A) and gj+8 (B)
    const int njA  = gj;
    const int wid  = tid >> 5;         // warp: k within tile = wid*4 + j2
    const int lane = tid & 31;

    // ================= Phase A: per-tensor max|.| (idempotent atomicMax) ==========
    {
        float lw = 0.f, lu = 0.f, lb = 0.f;
        const int gid = cta * TPB + tid;
        for (int i = gid; i < NDIM*NDIM; i += GRID*TPB) lw = fmaxf(lw, fabsf(W[i]));
        for (int i = gid; i < NDIM*DDIM; i += GRID*TPB) lu = fmaxf(lu, fabsf(U[i]));
        if (gid < NDIM) lb = fabsf(bvec[gid]);
        lw = warpmax(lw); lu = warpmax(lu); lb = warpmax(lb);
        if (lane == 0) { sm[wid] = lw; sm[16 + wid] = lu; sm[32 + wid] = lb; }
        __syncthreads();
        if (tid == 0) {
            float mw = 0.f, mu = 0.f, mb = 0.f;
            #pragma unroll
            for (int i = 0; i < 16; ++i) {
                mw = fmaxf(mw, sm[i]); mu = fmaxf(mu, sm[16+i]); mb = fmaxf(mb, sm[32+i]);
            }
            atomicMax(&g_maxW, __float_as_uint(mw));
            atomicMax(&g_maxU, __float_as_uint(mu));
            atomicMax(&g_maxB, __float_as_uint(mb));
        }
    }
    gbar(&g_gcnt, &g_ggen, GRID);   // the ONLY grid barrier

    const float scW = __uint_as_float(__ldcg(&g_maxW)) / QMAX;
    const float scU = __uint_as_float(__ldcg(&g_maxU)) / QMAX;
    const float scB = __uint_as_float(__ldcg(&g_maxB)) / QMAX;

    // ================= Phase B: Ux for BOTH groups (one row-dot pair per thread) ===
    {
        float* xs = sm;            // [784][16]: cols 0..7 group A, 8..15 group B
        float* uq = sm + 12544;    // [64][116] quantized U chunk
        const int r = tid >> 3;
        const int c = tid & 7;
        for (int i = tid; i < DDIM*16; i += TPB) {
            const int k = i >> 4, cc = i & 15;
            const int batch = (cc < 8) ? (gj*8 + cc) : ((gj + 8)*8 + (cc - 8));
            xs[i] = x[(size_t)batch*DDIM + k];
        }
        float accA = 0.f, accB = 0.f;
        for (int ch = 0; ch < 7; ++ch) {
            __syncthreads();
            for (int i = tid; i < 64*112; i += TPB) {
                const int rr = i / 112, kk = i - rr*112;
                uq[rr*116 + kk] = rintf(U[(size_t)(mi*64 + rr)*DDIM + ch*112 + kk] / scU) * scU;
            }
            __syncthreads();
            const float* up = uq + r*116;
            const float* xp = xs + ch*112*16 + c;
            #pragma unroll 4
            for (int kk = 0; kk < 112; ++kk) {
                const float uw = up[kk];
                accA = fmaf(uw, xp[kk*16],     accA);
                accB = fmaf(uw, xp[kk*16 + 8], accB);
            }
        }
        const float bq = rintf(bvec[mi*64 + r] / scB) * scB;
        __syncthreads();                 // scratch reads done before sZ/sRed reuse
        sUx[tid]       = accA + bq;
        sUx[512 + tid] = accB + bq;
    }

    // ================= Phase C: quantized W -> per-thread scalar registers =========
    float w0[32], w1[32];
    {
        const float* Wr0 = W + (size_t)(mi*64 + 2*lane)*NDIM;
        const float* Wr1 = Wr0 + NDIM;
        #pragma unroll
        for (int t = 0; t < 8; ++t) {
            const int k0 = t*64 + wid*4;
            const float4 a = *(const float4*)(Wr0 + k0);
            const float4 b = *(const float4*)(Wr1 + k0);
            w0[t*4+0] = rintf(a.x/scW)*scW; w0[t*4+1] = rintf(a.y/scW)*scW;
            w0[t*4+2] = rintf(a.z/scW)*scW; w0[t*4+3] = rintf(a.w/scW)*scW;
            w1[t*4+0] = rintf(b.x/scW)*scW; w1[t*4+1] = rintf(b.y/scW)*scW;
            w1[t*4+2] = rintf(b.z/scW)*scW; w1[t*4+3] = rintf(b.w/scW)*scW;
        }
    }

    // per-thread z output coordinates (combine mapping)
    const int orow  = tid >> 3;            // own-tile row 0..63
    const int ocol  = tid & 7;
    const int growN = mi*64 + orow;        // global row within group
    const int gbA   = njA*4096;            // group A z-block offset (B = gbA+32768)
    unsigned* rgA0  = &g_rgen[0][njA*NDIM];  // buffer A gens (B group = +4096)
    unsigned* rgA1  = &g_rgen[1][njA*NDIM];

    // ================= z1 = relu(0.5*Ux): both groups, publish data+gen ============
    float z_prevA, z_prevB;
    {
        const float z1A = fmaxf(0.5f * sUx[tid],       0.f);
        const float z1B = fmaxf(0.5f * sUx[512 + tid], 0.f);
        z_prevA = z1A; z_prevB = z1B;
        sZA[growN*ZSTR + ocol] = z1A;
        sZB[growN*ZSTR + ocol] = z1B;
        __stcg(&g_zA[gbA + mi*512 + tid],         z1A);
        __stcg(&g_zA[gbA + 32768 + mi*512 + tid], z1B);
        __syncwarp();
        if (ocol == 0) {
            gen_store(&rgA0[growN],        1u);
            gen_store(&rgA0[4096 + growN], 1u);
        }
    }
    float* gz_cur = g_zA;
    float* gz_nxt = g_zB;
    unsigned* rg_cur = rgA0;
    unsigned* rg_nxt = rgA1;

    // per-warp staging assignment: lane < 28 stages one remote row per group
    int st_row = -1;
    if (lane < 28) {
        int t = lane >> 2; t += (t >= mi);
        st_row = t*64 + wid*4 + (lane & 3);
    }
    const int coff = (tid >> 4)*20 + ((tid >> 3) & 1)*8 + (tid & 7);

    // ================= Main loop: 39 iterations, two interleaved groups ============
    for (int it = 2; it <= ITERS; ++it) {
        const unsigned tg = (unsigned)(it - 1);

        // ======================= GROUP A =======================
        {
            ull a00=0,a01=0,a02=0,a03=0, a10=0,a11=0,a12=0,a13=0;
            // own-tile GEMM (warp-local rows; overlaps peers' publish)
            {
                const float* zt = sZA + (mi*64 + wid*4)*ZSTR;
                #pragma unroll
                for (int j2 = 0; j2 < 4; ++j2) {
                    const float* q = zt + j2*ZSTR;
                    const ulonglong2 zA = *(const ulonglong2*)(q);
                    const ulonglong2 zB = *(const ulonglong2*)(q + 4);
                    const ull wd0 = pk2(w0[mi*4+j2]);
                    const ull wd1 = pk2(w1[mi*4+j2]);
                    fma2(a00, wd0, zA.x); fma2(a01, wd0, zA.y);
                    fma2(a02, wd0, zB.x); fma2(a03, wd0, zB.y);
                    fma2(a10, wd1, zA.x); fma2(a11, wd1, zA.y);
                    fma2(a12, wd1, zB.x); fma2(a13, wd1, zB.y);
                }
            }
            // poll row gens + stage remote rows (group A)
            if (lane < 28) {
                while (gen_acq(&rg_cur[st_row]) != tg) { }
                const float* src = gz_cur + gbA + st_row*8;
                const float4 a = __ldcg((const float4*)src);
                const float4 b = __ldcg((const float4*)(src + 4));
                *(float4*)(sZA + st_row*ZSTR)     = a;
                *(float4*)(sZA + st_row*ZSTR + 4) = b;
            }
            __syncwarp();
            // remote-tile GEMM
            #pragma unroll
            for (int t = 0; t < 8; ++t) {
                if (t == mi) continue;
                const float* zt = sZA + (t*64 + wid*4)*ZSTR;
                #pragma unroll
                for (int j2 = 0; j2 < 4; ++j2) {
                    const float* q = zt + j2*ZSTR;
                    const ulonglong2 zA = *(const ulonglong2*)(q);
                    const ulonglong2 zB = *(const ulonglong2*)(q + 4);
                    const ull wd0 = pk2(w0[t*4+j2]);
                    const ull wd1 = pk2(w1[t*4+j2]);
                    fma2(a00, wd0, zA.x); fma2(a01, wd0, zA.y);
                    fma2(a02, wd0, zB.x); fma2(a03, wd0, zB.y);
                    fma2(a10, wd1, zA.x); fma2(a11, wd1, zA.y);
                    fma2(a12, wd1, zB.x); fma2(a13, wd1, zB.y);
                }
            }
            // partials
            {
                float* rp = sRedA + wid*640 + lane*20;
                ulonglong2 s0; s0.x = a00; s0.y = a01; *(ulonglong2*)(rp)      = s0;
                ulonglong2 s1; s1.x = a02; s1.y = a03; *(ulonglong2*)(rp + 4)  = s1;
                ulonglong2 s2; s2.x = a10; s2.y = a11; *(ulonglong2*)(rp + 8)  = s2;
                ulonglong2 s3; s3.x = a12; s3.y = a13; *(ulonglong2*)(rp + 12) = s3;
            }
            __syncthreads();    // sync #1
            // combine + relu + publish (A)
            {
                float s = 0.f;
                const float* rq = sRedA + coff;
                #pragma unroll
                for (int q = 0; q < 16; ++q) s += rq[q*640];
                const float u  = sUx[tid];
                const float v  = fmaf(0.5f, z_prevA, 0.5f * (s + u));
                const float zn = fmaxf(v, 0.f);
                z_prevA = zn;
                sZA[growN*ZSTR + ocol] = zn;
                __stcg(&gz_nxt[gbA + mi*512 + tid], zn);
                __syncwarp();
                if (ocol == 0) gen_store(&rg_nxt[growN], (unsigned)it);
            }
        }

        // ======================= GROUP B =======================
        {
            ull a00=0,a01=0,a02=0,a03=0, a10=0,a11=0,a12=0,a13=0;
            {
                const float* zt = sZB + (mi*64 + wid*4)*ZSTR;
                #pragma unroll
                for (int j2 = 0; j2 < 4; ++j2) {
                    const float* q = zt + j2*ZSTR;
                    const ulonglong2 zA = *(const ulonglong2*)(q);
                    const ulonglong2 zB = *(const ulonglong2*)(q + 4);
                    const ull wd0 = pk2(w0[mi*4+j2]);
                    const ull wd1 = pk2(w1[mi*4+j2]);
                    fma2(a00, wd0, zA.x); fma2(a01, wd0, zA.y);
                    fma2(a02, wd0, zB.x); fma2(a03, wd0, zB.y);
                    fma2(a10, wd1, zA.x); fma2(a11, wd1, zA.y);
                    fma2(a12, wd1, zB.x); fma2(a13, wd1, zB.y);
                }
            }
            if (lane < 28) {
                while (gen_acq(&rg_cur[4096 + st_row]) != tg) { }
                const float* src = gz_cur + gbA + 32768 + st_row*8;
                const float4 a = __ldcg((const float4*)src);
                const float4 b = __ldcg((const float4*)(src + 4));
                *(float4*)(sZB + st_row*ZSTR)     = a;
                *(float4*)(sZB + st_row*ZSTR + 4) = b;
            }
            __syncwarp();
            #pragma unroll
            for (int t = 0; t < 8; ++t) {
                if (t == mi) continue;
                const float* zt = sZB + (t*64 + wid*4)*ZSTR;
                #pragma unroll
                for (int j2 = 0; j2 < 4; ++j2) {
                    const float* q = zt + j2*ZSTR;
                    const ulonglong2 zA = *(const ulonglong2*)(q);
                    const ulonglong2 zB = *(const ulonglong2*)(q + 4);
                    const ull wd0 = pk2(w0[t*4+j2]);
                    const ull wd1 = pk2(w1[t*4+j2]);
                    fma2(a00, wd0, zA.x); fma2(a01, wd0, zA.y);
                    fma2(a02, wd0, zB.x); fma2(a03, wd0, zB.y);
                    fma2(a10, wd1, zA.x); fma2(a11, wd1, zA.y);
                    fma2(a12, wd1, zB.x); fma2(a13, wd1, zB.y);
                }
            }
            {
                float* rp = sRedB + wid*640 + lane*20;
                ulonglong2 s0; s0.x = a00; s0.y = a01; *(ulonglong2*)(rp)      = s0;
                ulonglong2 s1; s1.x = a02; s1.y = a03; *(ulonglong2*)(rp + 4)  = s1;
                ulonglong2 s2; s2.x = a10; s2.y = a11; *(ulonglong2*)(rp + 8)  = s2;
                ulonglong2 s3; s3.x = a12; s3.y = a13; *(ulonglong2*)(rp + 12) = s3;
            }
            __syncthreads();    // sync #2
            {
                float s = 0.f;
                const float* rq = sRedB + coff;
                #pragma unroll
                for (int q = 0; q < 16; ++q) s += rq[q*640];
                const float u  = sUx[512 + tid];
                const float v  = fmaf(0.5f, z_prevB, 0.5f * (s + u));
                const float zn = fmaxf(v, 0.f);
                z_prevB = zn;
                sZB[growN*ZSTR + ocol] = zn;
                __stcg(&gz_nxt[gbA + 32768 + mi*512 + tid], zn);
                __syncwarp();
                if (ocol == 0) gen_store(&rg_nxt[4096 + growN], (unsigned)it);
            }
        }

        { float* t = gz_cur; gz_cur = gz_nxt; gz_nxt = t; }
        { unsigned* t = rg_cur; rg_cur = rg_nxt; rg_nxt = t; }
    }

    // ================= Classifier (row-tile 0 CTA; both groups) ====================
    if (mi == 0) {
        // stage z40 (in g_zB / gen buffer 1): one thread per global row, each group
        {
            while (gen_acq(&rgA1[tid]) != (unsigned)ITERS) { }
            const float* src = g_zB + gbA + tid*8;
            *(float4*)(sZA + tid*ZSTR)     = __ldcg((const float4*)src);
            *(float4*)(sZA + tid*ZSTR + 4) = __ldcg((const float4*)(src + 4));
        }
        {
            while (gen_acq(&rgA1[4096 + tid]) != (unsigned)ITERS) { }
            const float* src = g_zB + gbA + 32768 + tid*8;
            *(float4*)(sZB + tid*ZSTR)     = __ldcg((const float4*)src);
            *(float4*)(sZB + tid*ZSTR + 4) = __ldcg((const float4*)(src + 4));
        }
        __syncthreads();
        if (tid < 16*CDIM) {
            const int bl = tid / CDIM, cc = tid - bl*CDIM;
            const int c  = bl & 7;
            const float* zsrc = (bl < 8) ? sZA : sZB;
            const int nj = (bl < 8) ? njA : (njA + 8);
            const float* wc = Wc + cc*NDIM;
            float acc = bcv[cc];
            #pragma unroll 8
            for (int n = 0; n < NDIM; ++n)
                acc = fmaf(zsrc[n*ZSTR + c], wc[n], acc);
            out[(nj*8 + c)*CDIM + cc] = acc;
        }
    }
}

extern "C" void kernel_launch(void* const* d_in, const int* in_sizes, int n_in,
                              void* d_out, int out_size) {
    (void)in_sizes; (void)n_in; (void)out_size;
    cudaFuncSetAttribute(mondeq_kernel, cudaFuncAttributeMaxDynamicSharedMemorySize, SMEM_BYTES);
    mondeq_kernel<<<GRID, TPB, SMEM_BYTES>>>(
        (const float*)d_in[0],   // W  (512,512)
        (const float*)d_in[1],   // U  (512,784)
        (const float*)d_in[2],   // b  (512)
        (const float*)d_in[3],   // x  (128,784)
        (const float*)d_in[4],   // Wc (10,512)
        (const float*)d_in[5],   // bc (10)
        (float*)d_out);          // logits (128,10)
}

// round 16
// speedup vs baseline: 1.2568x; 1.2568x over previous
#include <cuda_runtime.h>
#include <math.h>

typedef unsigned long long ull;

#define NDIM 512
#define DDIM 784
#define CDIM 10
#define ITERS 40
#define QMAX 127.0f

#define MT 8          // row tiles (64 rows each)
#define NT 16         // column groups (8 cols each)
#define GRID (MT*NT)  // 128 CTAs
#define TPB 1024      // 32 warps: warp w covers k = t*64 + w*2 + {0,1}
#define ZSTR 12       // padded z row stride (8 used + 4 pad)

// shared layout (float offsets)
#define S_Z    0          // 512*12 = 6144
#define S_RED  6144       // DOUBLE buffered: 2 x (32 warps * 640) = 40960
#define S_UX   47104      // 512
#define SMEM_FLOATS 47616
#define SMEM_BYTES (SMEM_FLOATS*4)
// Phase B scratch overlaps sZ/sRed: xs @0 (6272), uq @6272 (7424), pb @13696 (1024)

// ---- device globals (scratch) ----
__device__ float g_zA[NDIM*128];                 // z_j, j odd
__device__ float g_zB[NDIM*128];                 // z_j, j even
__device__ unsigned g_rgen[2][NT*NDIM];          // per-row generation words
__device__ unsigned g_maxW, g_maxU, g_maxB;      // idempotent atomicMax
__device__ unsigned g_gcnt, g_ggen;              // grid barrier (used once)

// -------- grid barrier (prologue only) --------
__device__ __forceinline__ void gbar(unsigned* cnt, unsigned* gen, unsigned expected) {
    __syncthreads();
    if (threadIdx.x == 0) {
        unsigned snap, t;
        asm volatile("ld.acquire.gpu.global.u32 %0, [%1];" : "=r"(snap) : "l"(gen) : "memory");
        asm volatile("atom.acq_rel.gpu.global.add.u32 %0, [%1], %2;"
                     : "=r"(t) : "l"(cnt), "r"(1u) : "memory");
        if (t == expected - 1u) {
            asm volatile("st.relaxed.gpu.global.u32 [%0], %1;" :: "l"(cnt), "r"(0u) : "memory");
            asm volatile("red.release.gpu.global.add.u32 [%0], %1;" :: "l"(gen), "r"(1u) : "memory");
        } else {
            unsigned g;
            do {
                asm volatile("ld.acquire.gpu.global.u32 %0, [%1];" : "=r"(g) : "l"(gen) : "memory");
            } while (g == snap);
        }
    }
    __syncthreads();
}

// -------- gen-word primitives --------
__device__ __forceinline__ void gen_store(unsigned* f, unsigned v) {
    asm volatile("st.release.gpu.global.u32 [%0], %1;" :: "l"(f), "r"(v) : "memory");
}
__device__ __forceinline__ unsigned gen_acq(const unsigned* f) {
    unsigned v;
    asm volatile("ld.acquire.gpu.global.u32 %0, [%1];" : "=r"(v) : "l"(f) : "memory");
    return v;
}

// -------- f32x2 helpers --------
__device__ __forceinline__ ull pk2(float x){
    ull d; asm("mov.b64 %0, {%1,%1};" : "=l"(d) : "r"(__float_as_uint(x))); return d;
}
__device__ __forceinline__ void fma2(ull& d, ull a, ull b){
    asm("fma.rn.f32x2 %0, %1, %2, %3;" : "=l"(d) : "l"(a), "l"(b), "l"(d));
}
__device__ __forceinline__ float warpmax(float v){
    #pragma unroll
    for (int o = 16; o; o >>= 1) v = fmaxf(v, __shfl_xor_sync(0xffffffffu, v, o));
    return v;
}

extern "C" __global__ void __launch_bounds__(TPB, 1)
mondeq_kernel(const float* __restrict__ W, const float* __restrict__ U,
              const float* __restrict__ bvec, const float* __restrict__ x,
              const float* __restrict__ Wc, const float* __restrict__ bcv,
              float* __restrict__ out)
{
    extern __shared__ float sm[];
    float* sZ   = sm + S_Z;
    float* sRed = sm + S_RED;
    float* sUx  = sm + S_UX;

    const int tid  = threadIdx.x;
    const int cta  = blockIdx.x;
    const int mi   = cta & (MT - 1);   // row tile 0..7
    const int nj   = cta >> 3;         // column group 0..15
    const int wid  = tid >> 5;         // warp 0..31: k = t*64 + wid*2 + j2
    const int lane = tid & 31;         // rows 2*lane, 2*lane+1 of own tile

    // ================= Phase A: per-tensor max|.| (idempotent atomicMax) ==========
    {
        float lw = 0.f, lu = 0.f, lb = 0.f;
        const int gid = cta * TPB + tid;
        for (int i = gid; i < NDIM*NDIM; i += GRID*TPB) lw = fmaxf(lw, fabsf(W[i]));
        for (int i = gid; i < NDIM*DDIM; i += GRID*TPB) lu = fmaxf(lu, fabsf(U[i]));
        if (gid < NDIM) lb = fabsf(bvec[gid]);
        lw = warpmax(lw); lu = warpmax(lu); lb = warpmax(lb);
        if (lane == 0) { sm[wid] = lw; sm[32 + wid] = lu; sm[64 + wid] = lb; }
        __syncthreads();
        if (tid == 0) {
            float mw = 0.f, mu = 0.f, mb = 0.f;
            #pragma unroll
            for (int i = 0; i < 32; ++i) {
                mw = fmaxf(mw, sm[i]); mu = fmaxf(mu, sm[32+i]); mb = fmaxf(mb, sm[64+i]);
            }
            atomicMax(&g_maxW, __float_as_uint(mw));
            atomicMax(&g_maxU, __float_as_uint(mu));
            atomicMax(&g_maxB, __float_as_uint(mb));
        }
    }
    gbar(&g_gcnt, &g_ggen, GRID);   // the ONLY grid barrier

    const float scW = __uint_as_float(__ldcg(&g_maxW)) / QMAX;
    const float scU = __uint_as_float(__ldcg(&g_maxU)) / QMAX;
    const float scB = __uint_as_float(__ldcg(&g_maxB)) / QMAX;

    // ================= Phase B: Ux = Uq @ x^T + bq (k-range split across halves) ===
    {
        float* xs = sm;            // [784][8] k-major (6272)
        float* uq = sm + 6272;     // [64][116] quantized U chunk (7424)
        float* pb = sm + 13696;    // 1024 partials
        const int r    = (tid & 511) >> 3;
        const int c    = tid & 7;
        const int half = tid >> 9;
        for (int i = tid; i < DDIM*8; i += TPB) {
            const int k = i >> 3, cc = i & 7;
            xs[i] = x[(size_t)(nj*8 + cc)*DDIM + k];
        }
        float acc = 0.f;
        for (int ch = 0; ch < 7; ++ch) {
            __syncthreads();
            for (int i = tid; i < 64*112; i += TPB) {
                const int rr = i / 112, kk = i - rr*112;
                uq[rr*116 + kk] = rintf(U[(size_t)(mi*64 + rr)*DDIM + ch*112 + kk] / scU) * scU;
            }
            __syncthreads();
            if ((ch < 4) == (half == 0)) {
                const float* up = uq + r*116;
                const float* xp = xs + ch*112*8 + c;
                #pragma unroll 4
                for (int kk = 0; kk < 112; ++kk)
                    acc = fmaf(up[kk], xp[kk*8], acc);
            }
        }
        pb[tid] = acc;
        __syncthreads();
        if (tid < 512) {
            const float bq = rintf(bvec[mi*64 + (tid >> 3)] / scB) * scB;
            sUx[tid] = pb[tid] + pb[512 + tid] + bq;
        }
        __syncthreads();                 // scratch reads done before sZ reuse
    }

    // ================= Phase C: quantized W -> per-thread scalar registers =========
    // thread (wid, lane) holds rows {2*lane, 2*lane+1}, k = t*64 + wid*2 + j2
    float w0[16], w1[16];
    {
        const float* Wr0 = W + (size_t)(mi*64 + 2*lane)*NDIM;
        const float* Wr1 = Wr0 + NDIM;
        #pragma unroll
        for (int t = 0; t < 8; ++t) {
            const int k0 = t*64 + wid*2;
            const float2 a = *(const float2*)(Wr0 + k0);
            const float2 b = *(const float2*)(Wr1 + k0);
            w0[t*2+0] = rintf(a.x/scW)*scW; w0[t*2+1] = rintf(a.y/scW)*scW;
            w1[t*2+0] = rintf(b.x/scW)*scW; w1[t*2+1] = rintf(b.y/scW)*scW;
        }
    }

    // combine/output mapping: output o = tid>>1 (tid even = owner), helper = tid odd
    const int o    = tid >> 1;           // 0..511
    const int orow = o >> 3;             // own-tile row 0..63
    const int ocol = o & 7;
    const int growN = mi*64 + orow;
    unsigned* rg0 = &g_rgen[0][nj*NDIM];
    unsigned* rg1 = &g_rgen[1][nj*NDIM];

    // ================= z1 = relu(0.5*Ux): local + publish (data + gen) =============
    float z_prev = 0.f;
    {
        if ((tid & 1) == 0) {
            const float z1 = fmaxf(0.5f * sUx[o], 0.f);
            z_prev = z1;
            sZ[growN*ZSTR + ocol] = z1;
            __stcg(&g_zA[nj*4096 + mi*512 + o], z1);
        }
        __syncwarp();
        if ((tid & 15) == 0) gen_store(&rg0[growN], 1u);
    }
    float* gz_cur = g_zA;
    float* gz_nxt = g_zB;
    unsigned* rg_cur = rg0;
    unsigned* rg_nxt = rg1;

    // per-warp staging: lanes 0..13 stage one remote row each (7 tiles x 2 k-rows)
    int st_row = -1;
    if (lane < 14) {
        int t = lane >> 1; t += (t >= mi);
        st_row = t*64 + wid*2 + (lane & 1);
    }
    const int coff = (orow >> 1)*20 + (orow & 1)*8 + ocol + ((tid & 1) << 4)*640;

    // ================= Main loop: 39 iterations (z2..z40) ==========================
    for (int it = 2; it <= ITERS; ++it) {
        const int rb = it & 1;
        float* sRb = sRed + rb*20480;
        ull a00=0,a01=0,a02=0,a03=0, a10=0,a11=0,a12=0,a13=0;

        // ---- own-tile GEMM first (rows wid*2..+1 written by THIS warp's combine) --
        {
            const float* zt = sZ + (mi*64 + wid*2)*ZSTR;
            #pragma unroll
            for (int j2 = 0; j2 < 2; ++j2) {
                const float* q = zt + j2*ZSTR;
                const ulonglong2 zA = *(const ulonglong2*)(q);
                const ulonglong2 zB = *(const ulonglong2*)(q + 4);
                const ull wd0 = pk2(w0[mi*2+j2]);
                const ull wd1 = pk2(w1[mi*2+j2]);
                fma2(a00, wd0, zA.x); fma2(a01, wd0, zA.y);
                fma2(a02, wd0, zB.x); fma2(a03, wd0, zB.y);
                fma2(a10, wd1, zA.x); fma2(a11, wd1, zA.y);
                fma2(a12, wd1, zB.x); fma2(a13, wd1, zB.y);
            }
        }

        // ---- per-lane: poll row gen (data self-announces), then stage the row ----
        const unsigned tg = (unsigned)(it - 1);
        if (lane < 14) {
            const unsigned* gw = &rg_cur[st_row];
            while (gen_acq(gw) != tg) { }
            const float* src = gz_cur + nj*4096 + st_row*8;
            const float4 a = __ldcg((const float4*)src);
            const float4 b = __ldcg((const float4*)(src + 4));
            *(float4*)(sZ + st_row*ZSTR)     = a;
            *(float4*)(sZ + st_row*ZSTR + 4) = b;
        }
        __syncwarp();

        // ---- GEMM over the 7 remote tiles ----
        #pragma unroll
        for (int t = 0; t < 8; ++t) {
            if (t == mi) continue;
            const float* zt = sZ + (t*64 + wid*2)*ZSTR;
            #pragma unroll
            for (int j2 = 0; j2 < 2; ++j2) {
                const float* q = zt + j2*ZSTR;
                const ulonglong2 zA = *(const ulonglong2*)(q);
                const ulonglong2 zB = *(const ulonglong2*)(q + 4);
                const ull wd0 = pk2(w0[t*2+j2]);
                const ull wd1 = pk2(w1[t*2+j2]);
                fma2(a00, wd0, zA.x); fma2(a01, wd0, zA.y);
                fma2(a02, wd0, zB.x); fma2(a03, wd0, zB.y);
                fma2(a10, wd1, zA.x); fma2(a11, wd1, zA.y);
                fma2(a12, wd1, zB.x); fma2(a13, wd1, zB.y);
            }
        }

        // ---- partials: sRed[rb][wid*640 + lane*20 + {0..15}] ----
        {
            float* rp = sRb + wid*640 + lane*20;
            ulonglong2 s0; s0.x = a00; s0.y = a01; *(ulonglong2*)(rp)      = s0;
            ulonglong2 s1; s1.x = a02; s1.y = a03; *(ulonglong2*)(rp + 4)  = s1;
            ulonglong2 s2; s2.x = a10; s2.y = a11; *(ulonglong2*)(rp + 8)  = s2;
            ulonglong2 s3; s3.x = a12; s3.y = a13; *(ulonglong2*)(rp + 12) = s3;
        }
        __syncthreads();   // the single per-iteration CTA join (K reduction)

        // ---- combine: each thread sums 16 of 32 partials; pair-merge via shfl ----
        {
            float s = 0.f;
            const float* rq = sRb + coff;
            #pragma unroll
            for (int q = 0; q < 16; ++q) s += rq[q*640];
            s += __shfl_xor_sync(0xffffffffu, s, 1);
            if ((tid & 1) == 0) {
                const float u  = sUx[o];
                const float v  = fmaf(0.5f, z_prev, 0.5f * (s + u));
                const float zn = fmaxf(v, 0.f);
                z_prev = zn;
                sZ[growN*ZSTR + ocol] = zn;
                __stcg(&gz_nxt[nj*4096 + mi*512 + o], zn);
            }
            __syncwarp();          // warp's 2 rows fully stored (smem + global)
            if ((tid & 15) == 0) gen_store(&rg_nxt[growN], (unsigned)it);
        }

        { float* t = gz_cur; gz_cur = gz_nxt; gz_nxt = t; }
        { unsigned* t = rg_cur; rg_cur = rg_nxt; rg_nxt = t; }
    }

    // ================= Classifier (row-tile 0 CTA of each group) ====================
    if (mi == 0) {
        // stage z40 (buffer B, gen 40): one thread per global row
        if (tid < 512) {
            const unsigned* gw = &rg1[tid];
            while (gen_acq(gw) != (unsigned)ITERS) { }
            const float* src = g_zB + nj*4096 + tid*8;
            const float4 a = __ldcg((const float4*)src);
            const float4 b = __ldcg((const float4*)(src + 4));
            *(float4*)(sZ + tid*ZSTR)     = a;
            *(float4*)(sZ + tid*ZSTR + 4) = b;
        }
        __syncthreads();
        if (tid < 8*CDIM) {
            const int bl = tid / CDIM, cc = tid - bl*CDIM;
            const float* wc = Wc + cc*NDIM;
            float acc = bcv[cc];
            #pragma unroll 8
            for (int n = 0; n < NDIM; ++n)
                acc = fmaf(sZ[n*ZSTR + bl], wc[n], acc);
            out[(nj*8 + bl)*CDIM + cc] = acc;
        }
    }
}

extern "C" void kernel_launch(void* const* d_in, const int* in_sizes, int n_in,
                              void* d_out, int out_size) {
    (void)in_sizes; (void)n_in; (void)out_size;
    cudaFuncSetAttribute(mondeq_kernel, cudaFuncAttributeMaxDynamicSharedMemorySize, SMEM_BYTES);
    mondeq_kernel<<<GRID, TPB, SMEM_BYTES>>>(
        (const float*)d_in[0],   // W  (512,512)
        (const float*)d_in[1],   // U  (512,784)
        (const float*)d_in[2],   // b  (512)
        (const float*)d_in[3],   // x  (128,784)
        (const float*)d_in[4],   // Wc (10,512)
        (const float*)d_in[5],   // bc (10)
        (float*)d_out);          // logits (128,10)
}

// round 17
// speedup vs baseline: 1.3871x; 1.1037x over previous
#include <cuda_runtime.h>
#include <math.h>

typedef unsigned long long ull;

#define NDIM 512
#define DDIM 784
#define CDIM 10
#define ITERS 40
#define QMAX 127.0f

#define MT 8          // row tiles (64 rows each)
#define NT 16         // column groups (8 cols each)
#define GRID (MT*NT)  // 128 CTAs
#define TPB 512
#define ZSTR 12       // padded z row stride (8 used + 4 pad)

// shared layout (float offsets)
#define S_Z    0          // 512*12 = 6144 (single buffer, per-warp row ownership)
#define S_RED  6144       // DOUBLE buffered: 2 x (16 warps * 640) = 20480
#define S_UX   26624      // 512
#define SMEM_FLOATS 31744 // Phase B scratch needs 31616: xs @0 (6272), uq @6272 (64*396)
#define SMEM_BYTES (SMEM_FLOATS*4)

// ---- device globals (scratch) ----
__device__ float g_zA[NDIM*128];                 // z_j, j odd
__device__ float g_zB[NDIM*128];                 // z_j, j even
__device__ unsigned g_wgen[2][NT*128];           // per-(tile,warp) generation words
__device__ unsigned g_maxW, g_maxU, g_maxB;      // idempotent atomicMax
__device__ unsigned g_gcnt, g_ggen;              // grid barrier (used once)

// -------- grid barrier (prologue only) --------
__device__ __forceinline__ void gbar(unsigned* cnt, unsigned* gen, unsigned expected) {
    __syncthreads();
    if (threadIdx.x == 0) {
        unsigned snap, t;
        asm volatile("ld.acquire.gpu.global.u32 %0, [%1];" : "=r"(snap) : "l"(gen) : "memory");
        asm volatile("atom.acq_rel.gpu.global.add.u32 %0, [%1], %2;"
                     : "=r"(t) : "l"(cnt), "r"(1u) : "memory");
        if (t == expected - 1u) {
            asm volatile("st.relaxed.gpu.global.u32 [%0], %1;" :: "l"(cnt), "r"(0u) : "memory");
            asm volatile("red.release.gpu.global.add.u32 [%0], %1;" :: "l"(gen), "r"(1u) : "memory");
        } else {
            unsigned g;
            do {
                asm volatile("ld.acquire.gpu.global.u32 %0, [%1];" : "=r"(g) : "l"(gen) : "memory");
            } while (g == snap);
        }
    }
    __syncthreads();
}

// -------- gen-word primitives --------
__device__ __forceinline__ void gen_store(unsigned* f, unsigned v) {
    asm volatile("st.release.gpu.global.u32 [%0], %1;" :: "l"(f), "r"(v) : "memory");
}
__device__ __forceinline__ unsigned gen_acq(const unsigned* f) {
    unsigned v;
    asm volatile("ld.acquire.gpu.global.u32 %0, [%1];" : "=r"(v) : "l"(f) : "memory");
    return v;
}

// -------- f32x2 helpers --------
__device__ __forceinline__ ull pk2(float x){
    ull d; asm("mov.b64 %0, {%1,%1};" : "=l"(d) : "r"(__float_as_uint(x))); return d;
}
__device__ __forceinline__ void fma2(ull& d, ull a, ull b){
    asm("fma.rn.f32x2 %0, %1, %2, %3;" : "=l"(d) : "l"(a), "l"(b), "l"(d));
}
__device__ __forceinline__ float warpmax(float v){
    #pragma unroll
    for (int o = 16; o; o >>= 1) v = fmaxf(v, __shfl_xor_sync(0xffffffffu, v, o));
    return v;
}

extern "C" __global__ void __launch_bounds__(TPB, 1)
mondeq_kernel(const float* __restrict__ W, const float* __restrict__ U,
              const float* __restrict__ bvec, const float* __restrict__ x,
              const float* __restrict__ Wc, const float* __restrict__ bcv,
              float* __restrict__ out)
{
    extern __shared__ float sm[];
    float* sZ   = sm + S_Z;
    float* sRed = sm + S_RED;
    float* sUx  = sm + S_UX;

    const int tid  = threadIdx.x;
    const int cta  = blockIdx.x;
    const int mi   = cta & (MT - 1);   // row tile 0..7
    const int nj   = cta >> 3;         // column group 0..15
    const int wid  = tid >> 5;         // warp: k within tile = wid*4 + j2
    const int lane = tid & 31;         // rows 2*lane, 2*lane+1 of own tile

    // ================= Phase A: per-tensor max|.| (idempotent atomicMax) ==========
    {
        float lw = 0.f, lu = 0.f, lb = 0.f;
        const int gid = cta * TPB + tid;
        for (int i = gid; i < NDIM*NDIM; i += GRID*TPB) lw = fmaxf(lw, fabsf(W[i]));
        for (int i = gid; i < NDIM*DDIM; i += GRID*TPB) lu = fmaxf(lu, fabsf(U[i]));
        if (gid < NDIM) lb = fabsf(bvec[gid]);
        lw = warpmax(lw); lu = warpmax(lu); lb = warpmax(lb);
        if (lane == 0) { sm[wid] = lw; sm[16 + wid] = lu; sm[32 + wid] = lb; }
        __syncthreads();
        if (tid == 0) {
            float mw = 0.f, mu = 0.f, mb = 0.f;
            #pragma unroll
            for (int i = 0; i < 16; ++i) {
                mw = fmaxf(mw, sm[i]); mu = fmaxf(mu, sm[16+i]); mb = fmaxf(mb, sm[32+i]);
            }
            atomicMax(&g_maxW, __float_as_uint(mw));
            atomicMax(&g_maxU, __float_as_uint(mu));
            atomicMax(&g_maxB, __float_as_uint(mb));
        }
    }
    gbar(&g_gcnt, &g_ggen, GRID);   // the ONLY grid barrier

    const float scW = __uint_as_float(__ldcg(&g_maxW)) / QMAX;
    const float scU = __uint_as_float(__ldcg(&g_maxU)) / QMAX;
    const float scB = __uint_as_float(__ldcg(&g_maxB)) / QMAX;

    // ================= Phase B (group-local, 2 chunks): Ux = Uq @ x^T + bq =========
    {
        float* xs = sm;            // [784][8] transposed x cols (6272)
        float* uq = sm + 6272;     // [64][396] quantized U chunk (25344)
        const int r = tid >> 3;
        const int c = tid & 7;
        for (int i = tid; i < DDIM*8; i += TPB) {
            const int k = i >> 3, cc = i & 7;
            xs[i] = x[(size_t)(nj*8 + cc)*DDIM + k];
        }
        float acc = 0.f;
        for (int ch = 0; ch < 2; ++ch) {
            __syncthreads();
            for (int i = tid; i < 64*392; i += TPB) {
                const int rr = i / 392, kk = i - rr*392;
                uq[rr*396 + kk] = rintf(U[(size_t)(mi*64 + rr)*DDIM + ch*392 + kk] / scU) * scU;
            }
            __syncthreads();
            const float* up = uq + r*396;
            const float* xp = xs + ch*392*8 + c;
            #pragma unroll 4
            for (int kk = 0; kk < 392; ++kk)
                acc = fmaf(up[kk], xp[kk*8], acc);
        }
        const float bq = rintf(bvec[mi*64 + r] / scB) * scB;
        __syncthreads();                 // uq/xs reads done before sZ/sRed reuse
        sUx[tid] = acc + bq;
    }

    // ================= Phase C: quantized W -> per-thread scalar registers =========
    float w0[32], w1[32];
    {
        const float* Wr0 = W + (size_t)(mi*64 + 2*lane)*NDIM;
        const float* Wr1 = Wr0 + NDIM;
        #pragma unroll
        for (int t = 0; t < 8; ++t) {
            const int k0 = t*64 + wid*4;
            const float4 a = *(const float4*)(Wr0 + k0);
            const float4 b = *(const float4*)(Wr1 + k0);
            w0[t*4+0] = rintf(a.x/scW)*scW; w0[t*4+1] = rintf(a.y/scW)*scW;
            w0[t*4+2] = rintf(a.z/scW)*scW; w0[t*4+3] = rintf(a.w/scW)*scW;
            w1[t*4+0] = rintf(b.x/scW)*scW; w1[t*4+1] = rintf(b.y/scW)*scW;
            w1[t*4+2] = rintf(b.z/scW)*scW; w1[t*4+3] = rintf(b.w/scW)*scW;
        }
    }

    // per-thread z output coordinates (combine mapping)
    const int orow = tid >> 3;           // own-tile row 0..63 (warp w owns rows 4w..4w+3)
    const int ocol = tid & 7;
    const int growN = mi*64 + orow;      // global row within group
    unsigned* wg0 = &g_wgen[0][nj*128];  // gens for odd  z (z1, z3, ...)
    unsigned* wg1 = &g_wgen[1][nj*128];  // gens for even z

    // ================= z1 = relu(0.5*Ux): local + publish (data + per-warp gen) ====
    float z_prev;
    {
        const float z1 = fmaxf(0.5f * sUx[tid], 0.f);
        z_prev = z1;
        sZ[growN*ZSTR + ocol] = z1;
        __stcg(&g_zA[nj*4096 + mi*512 + tid], z1);
        __syncwarp();
        if (lane == 0) gen_store(&wg0[mi*16 + wid], 1u);
    }
    float* gz_cur = g_zA;
    float* gz_nxt = g_zB;
    unsigned* wg_cur = wg0;
    unsigned* wg_nxt = wg1;

    // per-warp staging assignment: lane < 28 stages one remote row it will consume;
    // 4 lanes per tile poll the SAME per-(tile,warp) gen word (coalesced).
    int st_row = -1, st_gen = -1;
    if (lane < 28) {
        int t = lane >> 2; t += (t >= mi);
        st_row = t*64 + wid*4 + (lane & 3);
        st_gen = t*16 + wid;
    }

    // ================= Main loop: 39 iterations (z2..z40) ==========================
    for (int it = 2; it <= ITERS; ++it) {
        const int rb = it & 1;                 // sRed buffer for this iteration
        float* sRb = sRed + rb*10240;
        ull a00=0,a01=0,a02=0,a03=0, a10=0,a11=0,a12=0,a13=0;

        // ---- own-tile GEMM first (rows 4*wid.. written by THIS warp's combine) ----
        {
            const float* zt = sZ + (mi*64 + wid*4)*ZSTR;
            #pragma unroll
            for (int j2 = 0; j2 < 4; ++j2) {
                const float* q = zt + j2*ZSTR;
                const ulonglong2 zA = *(const ulonglong2*)(q);
                const ulonglong2 zB = *(const ulonglong2*)(q + 4);
                const ull wd0 = pk2(w0[mi*4+j2]);
                const ull wd1 = pk2(w1[mi*4+j2]);
                fma2(a00, wd0, zA.x); fma2(a01, wd0, zA.y);
                fma2(a02, wd0, zB.x); fma2(a03, wd0, zB.y);
                fma2(a10, wd1, zA.x); fma2(a11, wd1, zA.y);
                fma2(a12, wd1, zB.x); fma2(a13, wd1, zB.y);
            }
        }

        // ---- per-lane: poll per-(tile,warp) gen, then stage the row ----
        const unsigned tg = (unsigned)(it - 1);
        if (lane < 28) {
            const unsigned* gw = &wg_cur[st_gen];
            while (gen_acq(gw) != tg) { }
            const float* src = gz_cur + nj*4096 + st_row*8;
            const float4 a = __ldcg((const float4*)src);
            const float4 b = __ldcg((const float4*)(src + 4));
            *(float4*)(sZ + st_row*ZSTR)     = a;
            *(float4*)(sZ + st_row*ZSTR + 4) = b;
        }
        __syncwarp();

        // ---- GEMM over the 7 remote tiles ----
        #pragma unroll
        for (int t = 0; t < 8; ++t) {
            if (t == mi) continue;
            const float* zt = sZ + (t*64 + wid*4)*ZSTR;
            #pragma unroll
            for (int j2 = 0; j2 < 4; ++j2) {
                const float* q = zt + j2*ZSTR;
                const ulonglong2 zA = *(const ulonglong2*)(q);
                const ulonglong2 zB = *(const ulonglong2*)(q + 4);
                const ull wd0 = pk2(w0[t*4+j2]);
                const ull wd1 = pk2(w1[t*4+j2]);
                fma2(a00, wd0, zA.x); fma2(a01, wd0, zA.y);
                fma2(a02, wd0, zB.x); fma2(a03, wd0, zB.y);
                fma2(a10, wd1, zA.x); fma2(a11, wd1, zA.y);
                fma2(a12, wd1, zB.x); fma2(a13, wd1, zB.y);
            }
        }

        // ---- partials: sRed[rb][wid*640 + lane*20 + {0..15}] ----
        {
            float* rp = sRb + wid*640 + lane*20;
            ulonglong2 s0; s0.x = a00; s0.y = a01; *(ulonglong2*)(rp)      = s0;
            ulonglong2 s1; s1.x = a02; s1.y = a03; *(ulonglong2*)(rp + 4)  = s1;
            ulonglong2 s2; s2.x = a10; s2.y = a11; *(ulonglong2*)(rp + 8)  = s2;
            ulonglong2 s3; s3.x = a12; s3.y = a13; *(ulonglong2*)(rp + 12) = s3;
        }
        __syncthreads();   // the single per-iteration CTA join (K reduction)

        // ---- combine + relu + publish (data, then ONE per-warp gen release) ----
        {
            const int coff = (tid >> 4)*20 + ((tid >> 3) & 1)*8 + (tid & 7);
            float s = 0.f;
            const float* rq = sRb + coff;
            #pragma unroll
            for (int q = 0; q < 16; ++q) s += rq[q*640];
            const float u  = sUx[tid];
            const float v  = fmaf(0.5f, z_prev, 0.5f * (s + u));
            const float zn = fmaxf(v, 0.f);
            z_prev = zn;
            sZ[growN*ZSTR + ocol] = zn;
            __stcg(&gz_nxt[nj*4096 + mi*512 + tid], zn);
            __syncwarp();          // warp's 4 rows fully stored (smem + global)
            if (lane == 0) gen_store(&wg_nxt[mi*16 + wid], (unsigned)it);
        }

        { float* t = gz_cur; gz_cur = gz_nxt; gz_nxt = t; }
        { unsigned* t = wg_cur; wg_cur = wg_nxt; wg_nxt = t; }
    }

    // ================= Classifier (row-tile 0 CTA of each group) ====================
    if (mi == 0) {
        // wait for z40 (buffer B, gen 40): 128 gen words, one per (tile,warp)
        if (tid < 128) {
            const unsigned* gw = &wg1[tid];
            while (gen_acq(gw) != (unsigned)ITERS) { }
        }
        __syncthreads();
        // stage all 512 rows of z40
        {
            const float* src = g_zB + nj*4096 + tid*8;
            const float4 a = __ldcg((const float4*)src);
            const float4 b = __ldcg((const float4*)(src + 4));
            *(float4*)(sZ + tid*ZSTR)     = a;
            *(float4*)(sZ + tid*ZSTR + 4) = b;
        }
        __syncthreads();
        if (tid < 8*CDIM) {
            const int bl = tid / CDIM, cc = tid - bl*CDIM;
            const float* wc = Wc + cc*NDIM;
            float acc = bcv[cc];
            #pragma unroll 8
            for (int n = 0; n < NDIM; ++n)
                acc = fmaf(sZ[n*ZSTR + bl], wc[n], acc);
            out[(nj*8 + bl)*CDIM + cc] = acc;
        }
    }
}

extern "C" void kernel_launch(void* const* d_in, const int* in_sizes, int n_in,
                              void* d_out, int out_size) {
    (void)in_sizes; (void)n_in; (void)out_size;
    cudaFuncSetAttribute(mondeq_kernel, cudaFuncAttributeMaxDynamicSharedMemorySize, SMEM_BYTES);
    mondeq_kernel<<<GRID, TPB, SMEM_BYTES>>>(
        (const float*)d_in[0],   // W  (512,512)
        (const float*)d_in[1],   // U  (512,784)
        (const float*)d_in[2],   // b  (512)
        (const float*)d_in[3],   // x  (128,784)
        (const float*)d_in[4],   // Wc (10,512)
        (const float*)d_in[5],   // bc (10)
        (float*)d_out);          // logits (128,10)
}